// round 1
// baseline (speedup 1.0000x reference)
#include <cuda_runtime.h>
#include <cstdint>
#include <math_constants.h>

// Causal MHA, BSHD, fp32 in/out, sm_scale = 1/sqrt(D).
// Flash-attention, TF32 mma.sync.m16n8k8, one CTA = (b, h, 64-row q tile).
// 4 warps/CTA, each warp owns 16 q rows. K/V tiles 32x128 in padded smem.

#define B_DIM 4
#define S_DIM 2048
#define H_DIM 16
#define D_DIM 128

#define BM 64          // q rows per CTA
#define BK 32          // kv rows per tile
#define KPAD 132       // padded row stride (floats) for K/V smem -> conflict-free frags
#define PPAD 36        // padded row stride for P smem
#define NWARPS 4

__device__ __forceinline__ uint32_t f2tf32(float f) {
    uint32_t r;
    asm("cvt.rna.tf32.f32 %0, %1;" : "=r"(r) : "f"(f));
    return r;
}

__device__ __forceinline__ void mma_tf32(float& c0, float& c1, float& c2, float& c3,
                                         uint32_t a0, uint32_t a1, uint32_t a2, uint32_t a3,
                                         uint32_t b0, uint32_t b1) {
    asm volatile(
        "mma.sync.aligned.m16n8k8.row.col.f32.tf32.tf32.f32 "
        "{%0,%1,%2,%3}, {%4,%5,%6,%7}, {%8,%9}, {%0,%1,%2,%3};"
        : "+f"(c0), "+f"(c1), "+f"(c2), "+f"(c3)
        : "r"(a0), "r"(a1), "r"(a2), "r"(a3), "r"(b0), "r"(b1));
}

__global__ __launch_bounds__(128) void MHAKernel_6691559047308_kernel(
    const float* __restrict__ Q,
    const float* __restrict__ K,
    const float* __restrict__ V,
    float* __restrict__ O) {

    __shared__ uint32_t Ks[BK][KPAD];
    __shared__ uint32_t Vs[BK][KPAD];
    __shared__ uint32_t Ps[NWARPS][16][PPAD];

    const int tid  = threadIdx.x;
    const int warp = tid >> 5;
    const int lane = tid & 31;
    const int g    = lane >> 2;   // groupID (row within fragment)
    const int tg   = lane & 3;    // threadID_in_group

    const int numQ = S_DIM / BM;  // 32
    const int bx   = blockIdx.x;
    // reverse q-tile order: heavy (late) causal tiles launch first
    const int qt = numQ - 1 - (bx % numQ);
    const int bh = bx / numQ;
    const int h  = bh % H_DIM;
    const int b  = bh / H_DIM;
    const int q0 = qt * BM;

    const float sm_scale = rsqrtf((float)D_DIM);
    const int rowstr = H_DIM * D_DIM;  // 2048 floats between seq positions

    const size_t bh_off = ((size_t)b * S_DIM) * rowstr + (size_t)h * D_DIM;
    const float* Qb = Q + bh_off;
    const float* Kb = K + bh_off;
    const float* Vb = V + bh_off;
    float*       Ob = O + bh_off;

    // ---- load Q fragments: 16 rows/warp, D=128 -> 16 k-chunks of 8 ----
    const int qrow0 = q0 + warp * 16;
    uint32_t qa[16][4];
    {
        const float* r0p = Qb + (size_t)(qrow0 + g) * rowstr;
        const float* r1p = Qb + (size_t)(qrow0 + g + 8) * rowstr;
        #pragma unroll
        for (int kc = 0; kc < 16; kc++) {
            const int c0 = kc * 8 + tg;
            qa[kc][0] = f2tf32(r0p[c0]     * sm_scale);
            qa[kc][1] = f2tf32(r1p[c0]     * sm_scale);
            qa[kc][2] = f2tf32(r0p[c0 + 4] * sm_scale);
            qa[kc][3] = f2tf32(r1p[c0 + 4] * sm_scale);
        }
    }

    // O accumulators: 16 n-chunks of 8 cols (D=128), C-fragment layout
    float o[16][4];
    #pragma unroll
    for (int i = 0; i < 16; i++) { o[i][0] = 0.f; o[i][1] = 0.f; o[i][2] = 0.f; o[i][3] = 0.f; }
    float m0 = -CUDART_INF_F, m1 = -CUDART_INF_F;  // running max, rows g / g+8
    float l0 = 0.f, l1 = 0.f;                      // running sum

    const int ntiles = (q0 + BM) / BK;

    for (int t = 0; t < ntiles; t++) {
        const int j0 = t * BK;

        // ---- cooperative load K,V tile (32 x 128) -> smem as tf32 ----
        #pragma unroll
        for (int i = 0; i < 8; i++) {
            const int v  = tid + i * 128;   // 1024 float4s total
            const int r  = v >> 5;          // 32 float4 per row
            const int c4 = v & 31;
            const float4 kv = *(const float4*)(Kb + (size_t)(j0 + r) * rowstr + c4 * 4);
            const float4 vv = *(const float4*)(Vb + (size_t)(j0 + r) * rowstr + c4 * 4);
            uint32_t* kd = &Ks[r][c4 * 4];
            kd[0] = f2tf32(kv.x); kd[1] = f2tf32(kv.y); kd[2] = f2tf32(kv.z); kd[3] = f2tf32(kv.w);
            uint32_t* vd = &Vs[r][c4 * 4];
            vd[0] = f2tf32(vv.x); vd[1] = f2tf32(vv.y); vd[2] = f2tf32(vv.z); vd[3] = f2tf32(vv.w);
        }
        __syncthreads();

        // ---- S = Q K^T : 16x32 per warp ----
        float s[4][4];
        #pragma unroll
        for (int nc = 0; nc < 4; nc++) { s[nc][0] = 0.f; s[nc][1] = 0.f; s[nc][2] = 0.f; s[nc][3] = 0.f; }
        #pragma unroll
        for (int kc = 0; kc < 16; kc++) {
            #pragma unroll
            for (int nc = 0; nc < 4; nc++) {
                const uint32_t b0 = Ks[nc * 8 + g][kc * 8 + tg];
                const uint32_t b1 = Ks[nc * 8 + g][kc * 8 + tg + 4];
                mma_tf32(s[nc][0], s[nc][1], s[nc][2], s[nc][3],
                         qa[kc][0], qa[kc][1], qa[kc][2], qa[kc][3], b0, b1);
            }
        }

        // ---- causal mask (only the last two tiles can touch the diagonal) ----
        if (j0 + BK > q0 + 1) {
            const int qr0 = qrow0 + g;
            const int qr1 = qrow0 + g + 8;
            #pragma unroll
            for (int nc = 0; nc < 4; nc++) {
                const int col = j0 + nc * 8 + 2 * tg;
                if (col     > qr0) s[nc][0] = -CUDART_INF_F;
                if (col + 1 > qr0) s[nc][1] = -CUDART_INF_F;
                if (col     > qr1) s[nc][2] = -CUDART_INF_F;
                if (col + 1 > qr1) s[nc][3] = -CUDART_INF_F;
            }
        }

        // ---- online softmax ----
        float rm0 = fmaxf(fmaxf(s[0][0], s[0][1]), fmaxf(s[1][0], s[1][1]));
        rm0 = fmaxf(rm0, fmaxf(fmaxf(s[2][0], s[2][1]), fmaxf(s[3][0], s[3][1])));
        float rm1 = fmaxf(fmaxf(s[0][2], s[0][3]), fmaxf(s[1][2], s[1][3]));
        rm1 = fmaxf(rm1, fmaxf(fmaxf(s[2][2], s[2][3]), fmaxf(s[3][2], s[3][3])));
        rm0 = fmaxf(rm0, __shfl_xor_sync(0xffffffffu, rm0, 1));
        rm0 = fmaxf(rm0, __shfl_xor_sync(0xffffffffu, rm0, 2));
        rm1 = fmaxf(rm1, __shfl_xor_sync(0xffffffffu, rm1, 1));
        rm1 = fmaxf(rm1, __shfl_xor_sync(0xffffffffu, rm1, 2));

        const float mn0 = fmaxf(m0, rm0);
        const float mn1 = fmaxf(m1, rm1);
        const float a0f = __expf(m0 - mn0);   // exp(-inf)=0 on first tile
        const float a1f = __expf(m1 - mn1);
        m0 = mn0; m1 = mn1;

        float rs0 = 0.f, rs1 = 0.f;
        #pragma unroll
        for (int nc = 0; nc < 4; nc++) {
            s[nc][0] = __expf(s[nc][0] - mn0);
            s[nc][1] = __expf(s[nc][1] - mn0);
            s[nc][2] = __expf(s[nc][2] - mn1);
            s[nc][3] = __expf(s[nc][3] - mn1);
            rs0 += s[nc][0] + s[nc][1];
            rs1 += s[nc][2] + s[nc][3];
        }
        rs0 += __shfl_xor_sync(0xffffffffu, rs0, 1);
        rs0 += __shfl_xor_sync(0xffffffffu, rs0, 2);
        rs1 += __shfl_xor_sync(0xffffffffu, rs1, 1);
        rs1 += __shfl_xor_sync(0xffffffffu, rs1, 2);
        l0 = l0 * a0f + rs0;
        l1 = l1 * a1f + rs1;

        // rescale O accumulators
        #pragma unroll
        for (int nc = 0; nc < 16; nc++) {
            o[nc][0] *= a0f; o[nc][1] *= a0f;
            o[nc][2] *= a1f; o[nc][3] *= a1f;
        }

        // ---- P -> smem (tf32) to re-fragment C-layout into A-layout ----
        #pragma unroll
        for (int nc = 0; nc < 4; nc++) {
            Ps[warp][g    ][nc * 8 + 2 * tg]     = f2tf32(s[nc][0]);
            Ps[warp][g    ][nc * 8 + 2 * tg + 1] = f2tf32(s[nc][1]);
            Ps[warp][g + 8][nc * 8 + 2 * tg]     = f2tf32(s[nc][2]);
            Ps[warp][g + 8][nc * 8 + 2 * tg + 1] = f2tf32(s[nc][3]);
        }
        __syncwarp();

        // ---- O += P V : (16x32) x (32x128) ----
        #pragma unroll
        for (int kc = 0; kc < 4; kc++) {
            const uint32_t pa0 = Ps[warp][g    ][kc * 8 + tg];
            const uint32_t pa1 = Ps[warp][g + 8][kc * 8 + tg];
            const uint32_t pa2 = Ps[warp][g    ][kc * 8 + tg + 4];
            const uint32_t pa3 = Ps[warp][g + 8][kc * 8 + tg + 4];
            #pragma unroll
            for (int nc = 0; nc < 16; nc++) {
                const uint32_t b0 = Vs[kc * 8 + tg    ][nc * 8 + g];
                const uint32_t b1 = Vs[kc * 8 + tg + 4][nc * 8 + g];
                mma_tf32(o[nc][0], o[nc][1], o[nc][2], o[nc][3], pa0, pa1, pa2, pa3, b0, b1);
            }
        }
        __syncthreads();   // protect K/V/P smem before next tile overwrite
    }

    // ---- epilogue: O /= l, store (cols 2tg,2tg+1 contiguous -> float2) ----
    const float il0 = 1.f / l0;
    const float il1 = 1.f / l1;
    float* out0 = Ob + (size_t)(qrow0 + g) * rowstr;
    float* out1 = Ob + (size_t)(qrow0 + g + 8) * rowstr;
    #pragma unroll
    for (int nc = 0; nc < 16; nc++) {
        float2 v0 = make_float2(o[nc][0] * il0, o[nc][1] * il0);
        float2 v1 = make_float2(o[nc][2] * il1, o[nc][3] * il1);
        *(float2*)(out0 + nc * 8 + 2 * tg) = v0;
        *(float2*)(out1 + nc * 8 + 2 * tg) = v1;
    }
}

extern "C" void kernel_launch(void* const* d_in, const int* in_sizes, int n_in,
                              void* d_out, int out_size) {
    const float* q = (const float*)d_in[0];
    const float* k = (const float*)d_in[1];
    const float* v = (const float*)d_in[2];
    float* o = (float*)d_out;

    const int numQ = S_DIM / BM;                 // 32
    const int grid = B_DIM * H_DIM * numQ;       // 2048
    MHAKernel_6691559047308_kernel<<<grid, 128>>>(q, k, v, o);
}